// round 1
// baseline (speedup 1.0000x reference)
#include <cuda_runtime.h>
#include <cuda_bf16.h>
#include <math.h>

// Problem constants
#define BATCH 4
#define SEQ   2048
#define EMBED 1024
#define HSZ   1024          // HEAD_SIZE
#define QKV3  3072          // 3*HSZ
#define BS    (BATCH*SEQ)   // 8192

// Scratch (device globals -- no allocation allowed)
__device__ float g_qkv[(size_t)BATCH * SEQ * QKV3];     // [B,S,3H]
__device__ float g_scores[(size_t)BATCH * SEQ * SEQ];   // [B,S,S]
__device__ float g_out[(size_t)BATCH * SEQ * HSZ];      // [B,S,H]
__device__ float g_outT[(size_t)BATCH * HSZ * SEQ];     // [B,H,S] (flat-view == out2)

// ---------------------------------------------------------------------------
// Tiled SGEMM: C = alpha * A * op(B) (+ bias[n]).
//   A: MxK row-major (lda)
//   B: TRANS_B ? NxK row-major (ldb), C[m,n] += A[m,k]*B[n,k]   (NT)
//              : KxN row-major (ldb), C[m,n] += A[m,k]*B[k,n]   (NN)
// Block tile 128x128, BK=16, thread tile 8x8, 256 threads.
// All dims must divide tiles (true for every call here).
// ---------------------------------------------------------------------------
template <bool TRANS_B, bool HAS_BIAS>
__global__ __launch_bounds__(256) void sgemm_kernel(
    const float* __restrict__ A, const float* __restrict__ B,
    float* __restrict__ C, const float* __restrict__ bias,
    int K, int lda, int ldb, int ldc,
    long long sA, long long sB, long long sC, float alpha)
{
    constexpr int BM = 128, BN = 128, BK = 16, TM = 8, TN = 8;
    __shared__ float As[BK][BM];
    __shared__ float Bs[BK][BN];

    A += (long long)blockIdx.z * sA;
    B += (long long)blockIdx.z * sB;
    C += (long long)blockIdx.z * sC;

    const int m0 = blockIdx.y * BM;
    const int n0 = blockIdx.x * BN;
    const int tid = threadIdx.x;
    const int row0 = (tid >> 4) * TM;   // 16 thread-cols
    const int col0 = (tid & 15) * TN;

    float acc[TM][TN];
#pragma unroll
    for (int i = 0; i < TM; i++)
#pragma unroll
        for (int j = 0; j < TN; j++) acc[i][j] = 0.f;

    for (int k0 = 0; k0 < K; k0 += BK) {
        // Load A tile (128 rows x 16 k), transposed into smem
#pragma unroll
        for (int i = 0; i < 2; i++) {
            int v = tid + i * 256;
            int r = v >> 2, c = (v & 3) << 2;
            float4 t = *reinterpret_cast<const float4*>(
                A + (size_t)(m0 + r) * lda + k0 + c);
            As[c + 0][r] = t.x; As[c + 1][r] = t.y;
            As[c + 2][r] = t.z; As[c + 3][r] = t.w;
        }
        if (TRANS_B) {
#pragma unroll
            for (int i = 0; i < 2; i++) {
                int v = tid + i * 256;
                int r = v >> 2, c = (v & 3) << 2;
                float4 t = *reinterpret_cast<const float4*>(
                    B + (size_t)(n0 + r) * ldb + k0 + c);
                Bs[c + 0][r] = t.x; Bs[c + 1][r] = t.y;
                Bs[c + 2][r] = t.z; Bs[c + 3][r] = t.w;
            }
        } else {
#pragma unroll
            for (int i = 0; i < 2; i++) {
                int v = tid + i * 256;
                int r = v >> 5, c = (v & 31) << 2;
                *reinterpret_cast<float4*>(&Bs[r][c]) =
                    *reinterpret_cast<const float4*>(
                        B + (size_t)(k0 + r) * ldb + n0 + c);
            }
        }
        __syncthreads();

#pragma unroll
        for (int kk = 0; kk < BK; kk++) {
            float a[TM], bb[TN];
#pragma unroll
            for (int i = 0; i < TM; i++) a[i] = As[kk][row0 + i];
#pragma unroll
            for (int j = 0; j < TN; j++) bb[j] = Bs[kk][col0 + j];
#pragma unroll
            for (int i = 0; i < TM; i++)
#pragma unroll
                for (int j = 0; j < TN; j++)
                    acc[i][j] = fmaf(a[i], bb[j], acc[i][j]);
        }
        __syncthreads();
    }

#pragma unroll
    for (int i = 0; i < TM; i++) {
#pragma unroll
        for (int j = 0; j < TN; j += 4) {
            float4 r;
            r.x = alpha * acc[i][j + 0];
            r.y = alpha * acc[i][j + 1];
            r.z = alpha * acc[i][j + 2];
            r.w = alpha * acc[i][j + 3];
            if (HAS_BIAS) {
                r.x += bias[n0 + col0 + j + 0];
                r.y += bias[n0 + col0 + j + 1];
                r.z += bias[n0 + col0 + j + 2];
                r.w += bias[n0 + col0 + j + 3];
            }
            *reinterpret_cast<float4*>(
                C + (size_t)(m0 + row0 + i) * ldc + n0 + col0 + j) = r;
        }
    }
}

// ---------------------------------------------------------------------------
// Row softmax, in place. One block (256 threads) per row of 2048 floats.
// ---------------------------------------------------------------------------
__global__ __launch_bounds__(256) void softmax_kernel(float* __restrict__ data)
{
    float* row = data + (size_t)blockIdx.x * SEQ;
    const int t = threadIdx.x;

    float v[8];
    float m = -INFINITY;
#pragma unroll
    for (int i = 0; i < 8; i++) {
        v[i] = row[t + i * 256];
        m = fmaxf(m, v[i]);
    }
#pragma unroll
    for (int o = 16; o > 0; o >>= 1)
        m = fmaxf(m, __shfl_xor_sync(0xffffffffu, m, o));

    __shared__ float redmax[8];
    __shared__ float redsum[8];
    if ((t & 31) == 0) redmax[t >> 5] = m;
    __syncthreads();
    float mm = redmax[0];
#pragma unroll
    for (int i = 1; i < 8; i++) mm = fmaxf(mm, redmax[i]);

    float s = 0.f;
#pragma unroll
    for (int i = 0; i < 8; i++) {
        v[i] = __expf(v[i] - mm);
        s += v[i];
    }
#pragma unroll
    for (int o = 16; o > 0; o >>= 1)
        s += __shfl_xor_sync(0xffffffffu, s, o);
    if ((t & 31) == 0) redsum[t >> 5] = s;
    __syncthreads();
    float ss = 0.f;
#pragma unroll
    for (int i = 0; i < 8; i++) ss += redsum[i];
    float inv = 1.0f / ss;

#pragma unroll
    for (int i = 0; i < 8; i++) row[t + i * 256] = v[i] * inv;
}

// ---------------------------------------------------------------------------
// Per-batch transpose: in [rows x cols] -> out [cols x rows]
// rows=SEQ=2048, cols=HSZ=1024. block (32,8), grid (cols/32, rows/32, BATCH).
// ---------------------------------------------------------------------------
__global__ __launch_bounds__(256) void transpose_kernel(
    const float* __restrict__ in, float* __restrict__ out)
{
    __shared__ float tile[32][33];
    const size_t base = (size_t)blockIdx.z * SEQ * HSZ;
    const int x0 = blockIdx.x * 32;   // col in `in`
    const int y0 = blockIdx.y * 32;   // row in `in`

#pragma unroll
    for (int i = threadIdx.y; i < 32; i += 8)
        tile[i][threadIdx.x] = in[base + (size_t)(y0 + i) * HSZ + x0 + threadIdx.x];
    __syncthreads();
#pragma unroll
    for (int i = threadIdx.y; i < 32; i += 8)
        out[base + (size_t)(x0 + i) * SEQ + y0 + threadIdx.x] = tile[threadIdx.x][i];
}

// ---------------------------------------------------------------------------
// Launch sequence (graph-capturable: kernel launches only)
// ---------------------------------------------------------------------------
extern "C" void kernel_launch(void* const* d_in, const int* in_sizes, int n_in,
                              void* d_out, int out_size)
{
    const float* x      = (const float*)d_in[0];   // [B,S,E]
    const float* w_qkv  = (const float*)d_in[1];   // [3H,E]
    const float* w_proj = (const float*)d_in[2];   // [E,H]
    const float* b_proj = (const float*)d_in[3];   // [E]
    float* y = (float*)d_out;                      // [B,S,E]

    float *qkv, *scores, *outb, *outT;
    cudaGetSymbolAddress((void**)&qkv,    g_qkv);
    cudaGetSymbolAddress((void**)&scores, g_scores);
    cudaGetSymbolAddress((void**)&outb,   g_out);
    cudaGetSymbolAddress((void**)&outT,   g_outT);

    const long long sQKV = (long long)SEQ * QKV3;
    const long long sSS  = (long long)SEQ * SEQ;
    const long long sSH  = (long long)SEQ * HSZ;

    // 1. qkv = x @ w_qkv^T          [8192 x 3072 x 1024] NT
    sgemm_kernel<true, false><<<dim3(QKV3 / 128, BS / 128, 1), 256>>>(
        x, w_qkv, qkv, nullptr, EMBED, EMBED, EMBED, QKV3, 0, 0, 0, 1.0f);

    // 2. scores = 0.125 * q @ k^T   batched 4x [2048 x 2048 x 1024] NT
    sgemm_kernel<true, false><<<dim3(SEQ / 128, SEQ / 128, BATCH), 256>>>(
        qkv, qkv + HSZ, scores, nullptr, HSZ, QKV3, QKV3, SEQ,
        sQKV, sQKV, sSS, 0.125f);

    // 3. row softmax (in place)
    softmax_kernel<<<BATCH * SEQ, 256>>>(scores);

    // 4. out = probs @ v            batched 4x [2048 x 1024 x 2048] NN
    sgemm_kernel<false, false><<<dim3(HSZ / 128, SEQ / 128, BATCH), 256>>>(
        scores, qkv + 2 * HSZ, outb, nullptr, SEQ, SEQ, QKV3, HSZ,
        sSS, sQKV, sSH, 1.0f);

    // 5. scrambling reshape == per-batch transpose then flat re-view
    transpose_kernel<<<dim3(HSZ / 32, SEQ / 32, BATCH), dim3(32, 8)>>>(outb, outT);

    // 6. y = out2 @ w_proj^T + b    [8192 x 1024 x 1024] NT + bias
    sgemm_kernel<true, true><<<dim3(EMBED / 128, BS / 128, 1), 256>>>(
        outT, w_proj, y, b_proj, HSZ, HSZ, HSZ, EMBED, 0, 0, 0, 1.0f);
}

// round 3
// speedup vs baseline: 2.9616x; 2.9616x over previous
#include <cuda_runtime.h>
#include <cuda_bf16.h>
#include <math.h>
#include <stdint.h>

// Problem constants
#define BATCH 4
#define SEQ   2048
#define EMBED 1024
#define HSZ   1024
#define QKV3  3072
#define BS    (BATCH*SEQ)

typedef __nv_bfloat16 bf16;

// Scratch (device globals -- no allocation allowed)
__device__ bf16  g_xh[(size_t)BS * EMBED];
__device__ bf16  g_xl[(size_t)BS * EMBED];
__device__ bf16  g_wqh[(size_t)QKV3 * EMBED];
__device__ bf16  g_wql[(size_t)QKV3 * EMBED];
__device__ bf16  g_wph[(size_t)EMBED * HSZ];
__device__ bf16  g_wpl[(size_t)EMBED * HSZ];
__device__ bf16  g_qkvh[(size_t)BS * QKV3];
__device__ bf16  g_qkvl[(size_t)BS * QKV3];
__device__ float g_scores[(size_t)BATCH * SEQ * SEQ];
__device__ bf16  g_ph[(size_t)BATCH * SEQ * SEQ];
__device__ bf16  g_pl[(size_t)BATCH * SEQ * SEQ];
__device__ bf16  g_vTh[(size_t)BATCH * HSZ * SEQ];
__device__ bf16  g_vTl[(size_t)BATCH * HSZ * SEQ];
__device__ bf16  g_oh[(size_t)BATCH * SEQ * HSZ];
__device__ bf16  g_ol[(size_t)BATCH * SEQ * HSZ];
__device__ bf16  g_oTh[(size_t)BATCH * HSZ * SEQ];
__device__ bf16  g_oTl[(size_t)BATCH * HSZ * SEQ];

// ---------------------------------------------------------------------------
__device__ __forceinline__ uint32_t smem_u32(const void* p) {
    uint32_t a;
    asm("{ .reg .u64 t; cvta.to.shared.u64 t, %1; cvt.u32.u64 %0, t; }"
        : "=r"(a) : "l"(p));
    return a;
}
__device__ __forceinline__ void cp16(uint32_t dst, const void* src) {
    asm volatile("cp.async.cg.shared.global [%0], [%1], 16;"
                 :: "r"(dst), "l"(src));
}
__device__ __forceinline__ void ldsm4(uint32_t* r, uint32_t addr) {
    asm volatile("ldmatrix.sync.aligned.m8n8.x4.shared.b16 {%0,%1,%2,%3}, [%4];"
                 : "=r"(r[0]), "=r"(r[1]), "=r"(r[2]), "=r"(r[3]) : "r"(addr));
}
__device__ __forceinline__ void mma16816(float* c, const uint32_t* a,
                                         const uint32_t* b) {
    asm volatile(
        "mma.sync.aligned.m16n8k16.row.col.f32.bf16.bf16.f32 "
        "{%0,%1,%2,%3}, {%4,%5,%6,%7}, {%8,%9}, {%0,%1,%2,%3};"
        : "+f"(c[0]), "+f"(c[1]), "+f"(c[2]), "+f"(c[3])
        : "r"(a[0]), "r"(a[1]), "r"(a[2]), "r"(a[3]), "r"(b[0]), "r"(b[1]));
}

// ---------------------------------------------------------------------------
// bf16x3 NT GEMM: C[m,n] = alpha * sum_k (Ah+Al)[m,k]*(Bh+Bl)[n,k]  (3 MMAs)
// Tile: BM=128, BN=256, BK=64. 256 threads = 8 warps (2m x 4n), warp 64x64.
// smem per stage: Ah16K Al16K Bh32K Bl32K = 96KB; 2 stages = 192KB.
// MODE 0: fp32 out; 1: fp32+bias; 2: split bf16 out (Ch,Cl)
// ---------------------------------------------------------------------------
template <int MODE>
__global__ __launch_bounds__(256) void tc_gemm(
    const bf16* __restrict__ Ah, const bf16* __restrict__ Al,
    const bf16* __restrict__ Bh, const bf16* __restrict__ Bl,
    float* __restrict__ C, bf16* __restrict__ Ch, bf16* __restrict__ Cl,
    const float* __restrict__ bias,
    int K, int lda, int ldb, int ldc,
    long long sA, long long sB, long long sC, float alpha)
{
    extern __shared__ char dsm[];
    const uint32_t base = smem_u32(dsm);

    const int tid = threadIdx.x;
    const int wid = tid >> 5, lane = tid & 31;
    const int wm = wid >> 2, wn = wid & 3;           // 2 x 4 warps
    const int gid = lane >> 2, tig = lane & 3;

    Ah += (long long)blockIdx.z * sA;  Al += (long long)blockIdx.z * sA;
    Bh += (long long)blockIdx.z * sB;  Bl += (long long)blockIdx.z * sB;
    const long long co = (long long)blockIdx.z * sC;
    const int m0 = blockIdx.y * 128;
    const int n0 = blockIdx.x * 256;

    // ldmatrix per-lane row/chunk decode
    const int rAl = lane & 15,                 cA16 = (lane >> 4) << 4;
    const int rBl = (lane & 7) | ((lane >> 4) << 3), cB16 = ((lane >> 3) & 1) << 4;

    uint32_t rbA[4], swA[4], rbB[4], swB[4];
#pragma unroll
    for (int mt = 0; mt < 4; mt++) {
        int row = wm * 64 + mt * 16 + rAl;
        rbA[mt] = (uint32_t)row << 7;
        swA[mt] = (uint32_t)(row & 7) << 4;
    }
#pragma unroll
    for (int np = 0; np < 4; np++) {
        int row = wn * 64 + np * 16 + rBl;
        rbB[np] = (uint32_t)row << 7;
        swB[np] = (uint32_t)(row & 7) << 4;
    }

    float c[4][8][4];
#pragma unroll
    for (int mt = 0; mt < 4; mt++)
#pragma unroll
        for (int nt = 0; nt < 8; nt++)
#pragma unroll
            for (int i = 0; i < 4; i++) c[mt][nt][i] = 0.f;

    const int NIT = K >> 6;

    auto load_stage = [&](int it, int s) {
        const uint32_t st = base + (uint32_t)s * 98304u;
        const int c0 = it << 6;
#pragma unroll
        for (int i = 0; i < 4; i++) {              // A tiles: 128 rows x 8 cp16
            int idx = tid + i * 256;
            int r = idx >> 3, ch = idx & 7;
            uint32_t off = ((uint32_t)r << 7) + (((uint32_t)ch << 4) ^ ((uint32_t)(r & 7) << 4));
            const bf16* gh = Ah + (size_t)(m0 + r) * lda + c0 + ch * 8;
            const bf16* gl = Al + (size_t)(m0 + r) * lda + c0 + ch * 8;
            cp16(st + off, gh);
            cp16(st + 16384u + off, gl);
        }
#pragma unroll
        for (int i = 0; i < 8; i++) {              // B tiles: 256 rows x 8 cp16
            int idx = tid + i * 256;
            int r = idx >> 3, ch = idx & 7;
            uint32_t off = ((uint32_t)r << 7) + (((uint32_t)ch << 4) ^ ((uint32_t)(r & 7) << 4));
            const bf16* gh = Bh + (size_t)(n0 + r) * ldb + c0 + ch * 8;
            const bf16* gl = Bl + (size_t)(n0 + r) * ldb + c0 + ch * 8;
            cp16(st + 32768u + off, gh);
            cp16(st + 65536u + off, gl);
        }
    };

    load_stage(0, 0);
    asm volatile("cp.async.commit_group;" ::: "memory");
    load_stage(1, 1);
    asm volatile("cp.async.commit_group;" ::: "memory");

#pragma unroll 1
    for (int it = 0; it < NIT; it++) {
        asm volatile("cp.async.wait_group 1;" ::: "memory");
        __syncthreads();

        const uint32_t st = base + (uint32_t)(it & 1) * 98304u;
#pragma unroll
        for (int ks = 0; ks < 4; ks++) {
            const uint32_t kb = (uint32_t)ks << 5;
            uint32_t ah[4][4], al[4][4];
#pragma unroll
            for (int mt = 0; mt < 4; mt++) {
                uint32_t a = st + rbA[mt] + ((kb + cA16) ^ swA[mt]);
                ldsm4(ah[mt], a);
                ldsm4(al[mt], a + 16384u);
            }
#pragma unroll
            for (int np = 0; np < 4; np++) {
                uint32_t bh[4], bl[4];
                uint32_t b = st + 32768u + rbB[np] + ((kb + cB16) ^ swB[np]);
                ldsm4(bh, b);
                ldsm4(bl, b + 32768u);
#pragma unroll
                for (int mt = 0; mt < 4; mt++) {
#pragma unroll
                    for (int h = 0; h < 2; h++) {
                        float* cc = c[mt][np * 2 + h];
                        mma16816(cc, ah[mt], bh + 2 * h);
                        mma16816(cc, ah[mt], bl + 2 * h);
                        mma16816(cc, al[mt], bh + 2 * h);
                    }
                }
            }
        }
        __syncthreads();
        if (it + 2 < NIT) load_stage(it + 2, it & 1);
        asm volatile("cp.async.commit_group;" ::: "memory");
    }

    // Epilogue
#pragma unroll
    for (int mt = 0; mt < 4; mt++) {
#pragma unroll
        for (int nt = 0; nt < 8; nt++) {
            int m = m0 + wm * 64 + mt * 16 + gid;
            int n = n0 + wn * 64 + nt * 8 + tig * 2;
            float v0 = alpha * c[mt][nt][0];
            float v1 = alpha * c[mt][nt][1];
            float v2 = alpha * c[mt][nt][2];
            float v3 = alpha * c[mt][nt][3];
            if (MODE == 1) {
                float b0 = bias[n], b1 = bias[n + 1];
                v0 += b0; v1 += b1; v2 += b0; v3 += b1;
            }
            if (MODE == 2) {
                bf16 h0 = __float2bfloat16(v0);
                bf16 h1 = __float2bfloat16(v1);
                bf16 h2 = __float2bfloat16(v2);
                bf16 h3 = __float2bfloat16(v3);
                bf16 l0 = __float2bfloat16(v0 - __bfloat162float(h0));
                bf16 l1 = __float2bfloat16(v1 - __bfloat162float(h1));
                bf16 l2 = __float2bfloat16(v2 - __bfloat162float(h2));
                bf16 l3 = __float2bfloat16(v3 - __bfloat162float(h3));
                __nv_bfloat162 hh0{h0, h1}, hh1{h2, h3};
                __nv_bfloat162 ll0{l0, l1}, ll1{l2, l3};
                *(__nv_bfloat162*)&Ch[co + (size_t)m * ldc + n]       = hh0;
                *(__nv_bfloat162*)&Ch[co + (size_t)(m + 8) * ldc + n] = hh1;
                *(__nv_bfloat162*)&Cl[co + (size_t)m * ldc + n]       = ll0;
                *(__nv_bfloat162*)&Cl[co + (size_t)(m + 8) * ldc + n] = ll1;
            } else {
                *(float2*)&C[co + (size_t)m * ldc + n]       = make_float2(v0, v1);
                *(float2*)&C[co + (size_t)(m + 8) * ldc + n] = make_float2(v2, v3);
            }
        }
    }
}

// ---------------------------------------------------------------------------
// Elementwise fp32 -> (hi, lo) bf16 split
// ---------------------------------------------------------------------------
__global__ __launch_bounds__(256) void split_kernel(
    const float* __restrict__ in, bf16* __restrict__ oh, bf16* __restrict__ ol,
    long long n)
{
    long long i = (long long)blockIdx.x * 256 + threadIdx.x;
    long long stride = (long long)gridDim.x * 256;
    for (; i < n; i += stride) {
        float v = in[i];
        bf16 h = __float2bfloat16(v);
        oh[i] = h;
        ol[i] = __float2bfloat16(v - __bfloat162float(h));
    }
}

// ---------------------------------------------------------------------------
// Row softmax: read fp32 scores, write split bf16 probs.
// ---------------------------------------------------------------------------
__global__ __launch_bounds__(256) void softmax_kernel(
    const float* __restrict__ scores, bf16* __restrict__ ph, bf16* __restrict__ pl)
{
    const float* row = scores + (size_t)blockIdx.x * SEQ;
    bf16* rh = ph + (size_t)blockIdx.x * SEQ;
    bf16* rl = pl + (size_t)blockIdx.x * SEQ;
    const int t = threadIdx.x;

    float v[8];
    float m = -INFINITY;
#pragma unroll
    for (int i = 0; i < 8; i++) {
        v[i] = row[t + i * 256];
        m = fmaxf(m, v[i]);
    }
#pragma unroll
    for (int o = 16; o > 0; o >>= 1)
        m = fmaxf(m, __shfl_xor_sync(0xffffffffu, m, o));

    __shared__ float redmax[8], redsum[8];
    if ((t & 31) == 0) redmax[t >> 5] = m;
    __syncthreads();
    float mm = redmax[0];
#pragma unroll
    for (int i = 1; i < 8; i++) mm = fmaxf(mm, redmax[i]);

    float s = 0.f;
#pragma unroll
    for (int i = 0; i < 8; i++) { v[i] = __expf(v[i] - mm); s += v[i]; }
#pragma unroll
    for (int o = 16; o > 0; o >>= 1)
        s += __shfl_xor_sync(0xffffffffu, s, o);
    if ((t & 31) == 0) redsum[t >> 5] = s;
    __syncthreads();
    float ss = 0.f;
#pragma unroll
    for (int i = 0; i < 8; i++) ss += redsum[i];
    float inv = 1.0f / ss;

#pragma unroll
    for (int i = 0; i < 8; i++) {
        float p = v[i] * inv;
        bf16 h = __float2bfloat16(p);
        rh[t + i * 256] = h;
        rl[t + i * 256] = __float2bfloat16(p - __bfloat162float(h));
    }
}

// ---------------------------------------------------------------------------
// Per-batch transpose of a bf16 (hi, lo) pair: out[c][r] = in[r][c]
// ---------------------------------------------------------------------------
__global__ __launch_bounds__(256) void transpose_pair(
    const bf16* __restrict__ inh, const bf16* __restrict__ inl,
    bf16* __restrict__ outh, bf16* __restrict__ outl,
    int ld_in, int ld_out, long long sIn, long long sOut)
{
    __shared__ bf16 th[32][33];
    __shared__ bf16 tl[32][33];
    inh += (long long)blockIdx.z * sIn;   inl += (long long)blockIdx.z * sIn;
    outh += (long long)blockIdx.z * sOut; outl += (long long)blockIdx.z * sOut;
    const int x0 = blockIdx.x * 32;
    const int y0 = blockIdx.y * 32;

#pragma unroll
    for (int i = threadIdx.y; i < 32; i += 8) {
        th[i][threadIdx.x] = inh[(size_t)(y0 + i) * ld_in + x0 + threadIdx.x];
        tl[i][threadIdx.x] = inl[(size_t)(y0 + i) * ld_in + x0 + threadIdx.x];
    }
    __syncthreads();
#pragma unroll
    for (int i = threadIdx.y; i < 32; i += 8) {
        outh[(size_t)(x0 + i) * ld_out + y0 + threadIdx.x] = th[threadIdx.x][i];
        outl[(size_t)(x0 + i) * ld_out + y0 + threadIdx.x] = tl[threadIdx.x][i];
    }
}

// ---------------------------------------------------------------------------
extern "C" void kernel_launch(void* const* d_in, const int* in_sizes, int n_in,
                              void* d_out, int out_size)
{
    const float* x      = (const float*)d_in[0];   // [B,S,E]
    const float* w_qkv  = (const float*)d_in[1];   // [3H,E]
    const float* w_proj = (const float*)d_in[2];   // [E,H]
    const float* b_proj = (const float*)d_in[3];   // [E]
    float* y = (float*)d_out;                      // [B,S,E]

    bf16 *xh, *xl, *wqh, *wql, *wph, *wpl, *qkvh, *qkvl;
    bf16 *ph, *pl, *vTh, *vTl, *oh, *ol, *oTh, *oTl;
    float* scores;
    cudaGetSymbolAddress((void**)&xh, g_xh);     cudaGetSymbolAddress((void**)&xl, g_xl);
    cudaGetSymbolAddress((void**)&wqh, g_wqh);   cudaGetSymbolAddress((void**)&wql, g_wql);
    cudaGetSymbolAddress((void**)&wph, g_wph);   cudaGetSymbolAddress((void**)&wpl, g_wpl);
    cudaGetSymbolAddress((void**)&qkvh, g_qkvh); cudaGetSymbolAddress((void**)&qkvl, g_qkvl);
    cudaGetSymbolAddress((void**)&scores, g_scores);
    cudaGetSymbolAddress((void**)&ph, g_ph);     cudaGetSymbolAddress((void**)&pl, g_pl);
    cudaGetSymbolAddress((void**)&vTh, g_vTh);   cudaGetSymbolAddress((void**)&vTl, g_vTl);
    cudaGetSymbolAddress((void**)&oh, g_oh);     cudaGetSymbolAddress((void**)&ol, g_ol);
    cudaGetSymbolAddress((void**)&oTh, g_oTh);   cudaGetSymbolAddress((void**)&oTl, g_oTl);

    const int shm = 196608;
    cudaFuncSetAttribute(tc_gemm<0>, cudaFuncAttributeMaxDynamicSharedMemorySize, shm);
    cudaFuncSetAttribute(tc_gemm<1>, cudaFuncAttributeMaxDynamicSharedMemorySize, shm);
    cudaFuncSetAttribute(tc_gemm<2>, cudaFuncAttributeMaxDynamicSharedMemorySize, shm);

    const long long sQKV = (long long)SEQ * QKV3;
    const long long sSS  = (long long)SEQ * SEQ;
    const long long sSH  = (long long)SEQ * HSZ;
    const long long sHS  = (long long)HSZ * SEQ;

    // 0. split inputs into bf16 (hi, lo)
    split_kernel<<<1024, 256>>>(x,      xh,  xl,  (long long)BS * EMBED);
    split_kernel<<<512,  256>>>(w_qkv,  wqh, wql, (long long)QKV3 * EMBED);
    split_kernel<<<256,  256>>>(w_proj, wph, wpl, (long long)EMBED * HSZ);

    // 1. qkv = x @ w_qkv^T   [8192 x 3072 x 1024], split output
    tc_gemm<2><<<dim3(QKV3 / 256, BS / 128, 1), 256, shm>>>(
        xh, xl, wqh, wql, nullptr, qkvh, qkvl, nullptr,
        EMBED, EMBED, EMBED, QKV3, 0, 0, 0, 1.0f);

    // 2. scores = 0.125 * q @ k^T   4x [2048 x 2048 x 1024], fp32 output
    tc_gemm<0><<<dim3(SEQ / 256, SEQ / 128, BATCH), 256, shm>>>(
        qkvh, qkvl, qkvh + HSZ, qkvl + HSZ, scores, nullptr, nullptr, nullptr,
        HSZ, QKV3, QKV3, SEQ, sQKV, sQKV, sSS, 0.125f);

    // 3. softmax -> split probs
    softmax_kernel<<<BATCH * SEQ, 256>>>(scores, ph, pl);

    // 4. vT = v^T per batch (v strided inside qkv split arrays)
    transpose_pair<<<dim3(HSZ / 32, SEQ / 32, BATCH), dim3(32, 8)>>>(
        qkvh + 2 * HSZ, qkvl + 2 * HSZ, vTh, vTl, QKV3, SEQ, sQKV, sHS);

    // 5. out = probs @ vT^T   4x [2048 x 1024 x 2048], split output
    tc_gemm<2><<<dim3(HSZ / 256, SEQ / 128, BATCH), 256, shm>>>(
        ph, pl, vTh, vTl, nullptr, oh, ol, nullptr,
        SEQ, SEQ, SEQ, HSZ, sSS, sHS, sSH, 1.0f);

    // 6. scrambling reshape == per-batch transpose (flat re-view)
    transpose_pair<<<dim3(HSZ / 32, SEQ / 32, BATCH), dim3(32, 8)>>>(
        oh, ol, oTh, oTl, HSZ, SEQ, sSH, sHS);

    // 7. y = out2 @ w_proj^T + b   [8192 x 1024 x 1024], fp32 + bias
    tc_gemm<1><<<dim3(EMBED / 256, BS / 128, 1), 256, shm>>>(
        oTh, oTl, wph, wpl, y, nullptr, nullptr, b_proj,
        HSZ, HSZ, HSZ, EMBED, 0, 0, 0, 1.0f);
}

// round 4
// speedup vs baseline: 2.9620x; 1.0001x over previous
#include <cuda_runtime.h>
#include <cuda_bf16.h>
#include <math.h>
#include <stdint.h>

// Problem constants
#define BATCH 4
#define SEQ   2048
#define EMBED 1024
#define HSZ   1024
#define QKV3  3072
#define BS    (BATCH*SEQ)

typedef __nv_bfloat16 bf16;

// Scratch (device globals -- no allocation allowed)
__device__ bf16  g_xh[(size_t)BS * EMBED];
__device__ bf16  g_xl[(size_t)BS * EMBED];
__device__ bf16  g_wqh[(size_t)QKV3 * EMBED];
__device__ bf16  g_wql[(size_t)QKV3 * EMBED];
__device__ bf16  g_wph[(size_t)EMBED * HSZ];
__device__ bf16  g_wpl[(size_t)EMBED * HSZ];
__device__ bf16  g_qkvh[(size_t)BS * QKV3];
__device__ bf16  g_qkvl[(size_t)BS * QKV3];
__device__ float g_scores[(size_t)BATCH * SEQ * SEQ];
__device__ bf16  g_ph[(size_t)BATCH * SEQ * SEQ];
__device__ bf16  g_pl[(size_t)BATCH * SEQ * SEQ];
__device__ bf16  g_vTh[(size_t)BATCH * HSZ * SEQ];
__device__ bf16  g_vTl[(size_t)BATCH * HSZ * SEQ];
__device__ bf16  g_oh[(size_t)BATCH * SEQ * HSZ];
__device__ bf16  g_ol[(size_t)BATCH * SEQ * HSZ];
__device__ bf16  g_oTh[(size_t)BATCH * HSZ * SEQ];
__device__ bf16  g_oTl[(size_t)BATCH * HSZ * SEQ];

// ---------------------------------------------------------------------------
__device__ __forceinline__ uint32_t smem_u32(const void* p) {
    uint32_t a;
    asm("{ .reg .u64 t; cvta.to.shared.u64 t, %1; cvt.u32.u64 %0, t; }"
        : "=r"(a) : "l"(p));
    return a;
}
__device__ __forceinline__ void cp16(uint32_t dst, const void* src) {
    asm volatile("cp.async.cg.shared.global [%0], [%1], 16;"
                 :: "r"(dst), "l"(src));
}
__device__ __forceinline__ void ldsm4(uint32_t* r, uint32_t addr) {
    asm volatile("ldmatrix.sync.aligned.m8n8.x4.shared.b16 {%0,%1,%2,%3}, [%4];"
                 : "=r"(r[0]), "=r"(r[1]), "=r"(r[2]), "=r"(r[3]) : "r"(addr));
}
__device__ __forceinline__ void mma16816(float* c, const uint32_t* a,
                                         const uint32_t* b) {
    asm volatile(
        "mma.sync.aligned.m16n8k16.row.col.f32.bf16.bf16.f32 "
        "{%0,%1,%2,%3}, {%4,%5,%6,%7}, {%8,%9}, {%0,%1,%2,%3};"
        : "+f"(c[0]), "+f"(c[1]), "+f"(c[2]), "+f"(c[3])
        : "r"(a[0]), "r"(a[1]), "r"(a[2]), "r"(a[3]), "r"(b[0]), "r"(b[1]));
}

// ---------------------------------------------------------------------------
// bf16x3 NT GEMM: C[m,n] = alpha * sum_k (Ah+Al)[m,k]*(Bh+Bl)[n,k]  (3 MMAs)
// Tile: BM = WMT*32 (128 or 64), BN = 128, BK = 64. 256 threads = 8 warps
// (2m x 4n); warp tile (WMT*16) x 32. 3-stage cp.async pipeline.
// MODE 0: fp32 out; 1: fp32+bias; 2: split bf16 out (Ch,Cl)
// ---------------------------------------------------------------------------
template <int MODE, int WMT>
__global__ __launch_bounds__(256) void tc_gemm(
    const bf16* __restrict__ Ah, const bf16* __restrict__ Al,
    const bf16* __restrict__ Bh, const bf16* __restrict__ Bl,
    float* __restrict__ C, bf16* __restrict__ Ch, bf16* __restrict__ Cl,
    const float* __restrict__ bias,
    int K, int lda, int ldb, int ldc,
    long long sA, long long sB, long long sC, float alpha)
{
    constexpr int BM = WMT * 32;                 // 128 or 64
    constexpr uint32_t A_LIMB = (uint32_t)BM * 128u;   // bytes per A limb tile
    constexpr uint32_t B_OFF  = 2u * A_LIMB;           // B tiles offset in stage
    constexpr uint32_t STAGE  = B_OFF + 32768u;        // stage stride
    constexpr int NSTG = 3;

    extern __shared__ char dsm[];
    const uint32_t base = smem_u32(dsm);

    const int tid = threadIdx.x;
    const int wid = tid >> 5, lane = tid & 31;
    const int wm = wid >> 2, wn = wid & 3;           // 2 x 4 warps
    const int gid = lane >> 2, tig = lane & 3;

    Ah += (long long)blockIdx.z * sA;  Al += (long long)blockIdx.z * sA;
    Bh += (long long)blockIdx.z * sB;  Bl += (long long)blockIdx.z * sB;
    const long long co = (long long)blockIdx.z * sC;
    const int m0 = blockIdx.y * BM;
    const int n0 = blockIdx.x * 128;

    // ldmatrix per-lane row/chunk decode
    const int rAl = lane & 15,                       cA16 = (lane >> 4) << 4;
    const int rBl = (lane & 7) | ((lane >> 4) << 3), cB16 = ((lane >> 3) & 1) << 4;

    uint32_t rbA[WMT], swA[WMT], rbB[2], swB[2];
#pragma unroll
    for (int mt = 0; mt < WMT; mt++) {
        int row = wm * (WMT * 16) + mt * 16 + rAl;
        rbA[mt] = (uint32_t)row << 7;
        swA[mt] = (uint32_t)(row & 7) << 4;
    }
#pragma unroll
    for (int np = 0; np < 2; np++) {
        int row = wn * 32 + np * 16 + rBl;
        rbB[np] = (uint32_t)row << 7;
        swB[np] = (uint32_t)(row & 7) << 4;
    }

    float c[WMT][4][4];
#pragma unroll
    for (int mt = 0; mt < WMT; mt++)
#pragma unroll
        for (int nt = 0; nt < 4; nt++)
#pragma unroll
            for (int i = 0; i < 4; i++) c[mt][nt][i] = 0.f;

    const int NIT = K >> 6;

    auto load_stage = [&](int it, int s) {
        const uint32_t st = base + (uint32_t)s * STAGE;
        const int c0 = it << 6;
#pragma unroll
        for (int i = 0; i < BM / 32; i++) {        // A: BM rows x 8 cp16
            int idx = tid + i * 256;
            int r = idx >> 3, ch = idx & 7;
            uint32_t off = ((uint32_t)r << 7) + (((uint32_t)ch << 4) ^ ((uint32_t)(r & 7) << 4));
            cp16(st + off,          Ah + (size_t)(m0 + r) * lda + c0 + ch * 8);
            cp16(st + A_LIMB + off, Al + (size_t)(m0 + r) * lda + c0 + ch * 8);
        }
#pragma unroll
        for (int i = 0; i < 4; i++) {              // B: 128 rows x 8 cp16
            int idx = tid + i * 256;
            int r = idx >> 3, ch = idx & 7;
            uint32_t off = ((uint32_t)r << 7) + (((uint32_t)ch << 4) ^ ((uint32_t)(r & 7) << 4));
            cp16(st + B_OFF + off,          Bh + (size_t)(n0 + r) * ldb + c0 + ch * 8);
            cp16(st + B_OFF + 16384u + off, Bl + (size_t)(n0 + r) * ldb + c0 + ch * 8);
        }
        asm volatile("cp.async.commit_group;" ::: "memory");
    };

    load_stage(0, 0);
    load_stage(1, 1);
    load_stage(2, 2);

#pragma unroll 1
    for (int it = 0; it < NIT; it++) {
        asm volatile("cp.async.wait_group 2;" ::: "memory");
        __syncthreads();

        const uint32_t st = base + (uint32_t)(it % NSTG) * STAGE;
#pragma unroll
        for (int ks = 0; ks < 4; ks++) {
            const uint32_t kb = (uint32_t)ks << 5;
            uint32_t ah[WMT][4], al[WMT][4];
#pragma unroll
            for (int mt = 0; mt < WMT; mt++) {
                uint32_t a = st + rbA[mt] + ((kb + cA16) ^ swA[mt]);
                ldsm4(ah[mt], a);
                ldsm4(al[mt], a + A_LIMB);
            }
#pragma unroll
            for (int np = 0; np < 2; np++) {
                uint32_t bh[4], bl[4];
                uint32_t b = st + B_OFF + rbB[np] + ((kb + cB16) ^ swB[np]);
                ldsm4(bh, b);
                ldsm4(bl, b + 16384u);
#pragma unroll
                for (int mt = 0; mt < WMT; mt++) {
#pragma unroll
                    for (int h = 0; h < 2; h++) {
                        float* cc = c[mt][np * 2 + h];
                        mma16816(cc, ah[mt], bh + 2 * h);
                        mma16816(cc, ah[mt], bl + 2 * h);
                        mma16816(cc, al[mt], bh + 2 * h);
                    }
                }
            }
        }
        __syncthreads();
        if (it + NSTG < NIT) load_stage(it + NSTG, it % NSTG);
        else asm volatile("cp.async.commit_group;" ::: "memory");
    }

    // Epilogue
#pragma unroll
    for (int mt = 0; mt < WMT; mt++) {
#pragma unroll
        for (int nt = 0; nt < 4; nt++) {
            int m = m0 + wm * (WMT * 16) + mt * 16 + gid;
            int n = n0 + wn * 32 + nt * 8 + tig * 2;
            float v0 = alpha * c[mt][nt][0];
            float v1 = alpha * c[mt][nt][1];
            float v2 = alpha * c[mt][nt][2];
            float v3 = alpha * c[mt][nt][3];
            if (MODE == 1) {
                float b0 = bias[n], b1 = bias[n + 1];
                v0 += b0; v1 += b1; v2 += b0; v3 += b1;
            }
            if (MODE == 2) {
                bf16 h0 = __float2bfloat16(v0);
                bf16 h1 = __float2bfloat16(v1);
                bf16 h2 = __float2bfloat16(v2);
                bf16 h3 = __float2bfloat16(v3);
                bf16 l0 = __float2bfloat16(v0 - __bfloat162float(h0));
                bf16 l1 = __float2bfloat16(v1 - __bfloat162float(h1));
                bf16 l2 = __float2bfloat16(v2 - __bfloat162float(h2));
                bf16 l3 = __float2bfloat16(v3 - __bfloat162float(h3));
                __nv_bfloat162 hh0{h0, h1}, hh1{h2, h3};
                __nv_bfloat162 ll0{l0, l1}, ll1{l2, l3};
                *(__nv_bfloat162*)&Ch[co + (size_t)m * ldc + n]       = hh0;
                *(__nv_bfloat162*)&Ch[co + (size_t)(m + 8) * ldc + n] = hh1;
                *(__nv_bfloat162*)&Cl[co + (size_t)m * ldc + n]       = ll0;
                *(__nv_bfloat162*)&Cl[co + (size_t)(m + 8) * ldc + n] = ll1;
            } else {
                *(float2*)&C[co + (size_t)m * ldc + n]       = make_float2(v0, v1);
                *(float2*)&C[co + (size_t)(m + 8) * ldc + n] = make_float2(v2, v3);
            }
        }
    }
}

// ---------------------------------------------------------------------------
// Elementwise fp32 -> (hi, lo) bf16 split
// ---------------------------------------------------------------------------
__global__ __launch_bounds__(256) void split_kernel(
    const float* __restrict__ in, bf16* __restrict__ oh, bf16* __restrict__ ol,
    long long n)
{
    long long i = (long long)blockIdx.x * 256 + threadIdx.x;
    long long stride = (long long)gridDim.x * 256;
    for (; i < n; i += stride) {
        float v = in[i];
        bf16 h = __float2bfloat16(v);
        oh[i] = h;
        ol[i] = __float2bfloat16(v - __bfloat162float(h));
    }
}

// ---------------------------------------------------------------------------
// Row softmax: read fp32 scores, write split bf16 probs.
// ---------------------------------------------------------------------------
__global__ __launch_bounds__(256) void softmax_kernel(
    const float* __restrict__ scores, bf16* __restrict__ ph, bf16* __restrict__ pl)
{
    const float* row = scores + (size_t)blockIdx.x * SEQ;
    bf16* rh = ph + (size_t)blockIdx.x * SEQ;
    bf16* rl = pl + (size_t)blockIdx.x * SEQ;
    const int t = threadIdx.x;

    float v[8];
    float m = -INFINITY;
#pragma unroll
    for (int i = 0; i < 8; i++) {
        v[i] = row[t + i * 256];
        m = fmaxf(m, v[i]);
    }
#pragma unroll
    for (int o = 16; o > 0; o >>= 1)
        m = fmaxf(m, __shfl_xor_sync(0xffffffffu, m, o));

    __shared__ float redmax[8], redsum[8];
    if ((t & 31) == 0) redmax[t >> 5] = m;
    __syncthreads();
    float mm = redmax[0];
#pragma unroll
    for (int i = 1; i < 8; i++) mm = fmaxf(mm, redmax[i]);

    float s = 0.f;
#pragma unroll
    for (int i = 0; i < 8; i++) { v[i] = __expf(v[i] - mm); s += v[i]; }
#pragma unroll
    for (int o = 16; o > 0; o >>= 1)
        s += __shfl_xor_sync(0xffffffffu, s, o);
    if ((t & 31) == 0) redsum[t >> 5] = s;
    __syncthreads();
    float ss = 0.f;
#pragma unroll
    for (int i = 0; i < 8; i++) ss += redsum[i];
    float inv = 1.0f / ss;

#pragma unroll
    for (int i = 0; i < 8; i++) {
        float p = v[i] * inv;
        bf16 h = __float2bfloat16(p);
        rh[t + i * 256] = h;
        rl[t + i * 256] = __float2bfloat16(p - __bfloat162float(h));
    }
}

// ---------------------------------------------------------------------------
// Per-batch transpose of a bf16 (hi, lo) pair: out[c][r] = in[r][c]
// ---------------------------------------------------------------------------
__global__ __launch_bounds__(256) void transpose_pair(
    const bf16* __restrict__ inh, const bf16* __restrict__ inl,
    bf16* __restrict__ outh, bf16* __restrict__ outl,
    int ld_in, int ld_out, long long sIn, long long sOut)
{
    __shared__ bf16 th[32][33];
    __shared__ bf16 tl[32][33];
    inh += (long long)blockIdx.z * sIn;   inl += (long long)blockIdx.z * sIn;
    outh += (long long)blockIdx.z * sOut; outl += (long long)blockIdx.z * sOut;
    const int x0 = blockIdx.x * 32;
    const int y0 = blockIdx.y * 32;

#pragma unroll
    for (int i = threadIdx.y; i < 32; i += 8) {
        th[i][threadIdx.x] = inh[(size_t)(y0 + i) * ld_in + x0 + threadIdx.x];
        tl[i][threadIdx.x] = inl[(size_t)(y0 + i) * ld_in + x0 + threadIdx.x];
    }
    __syncthreads();
#pragma unroll
    for (int i = threadIdx.y; i < 32; i += 8) {
        outh[(size_t)(x0 + i) * ld_out + y0 + threadIdx.x] = th[threadIdx.x][i];
        outl[(size_t)(x0 + i) * ld_out + y0 + threadIdx.x] = tl[threadIdx.x][i];
    }
}

// ---------------------------------------------------------------------------
extern "C" void kernel_launch(void* const* d_in, const int* in_sizes, int n_in,
                              void* d_out, int out_size)
{
    const float* x      = (const float*)d_in[0];   // [B,S,E]
    const float* w_qkv  = (const float*)d_in[1];   // [3H,E]
    const float* w_proj = (const float*)d_in[2];   // [E,H]
    const float* b_proj = (const float*)d_in[3];   // [E]
    float* y = (float*)d_out;                      // [B,S,E]

    bf16 *xh, *xl, *wqh, *wql, *wph, *wpl, *qkvh, *qkvl;
    bf16 *ph, *pl, *vTh, *vTl, *oh, *ol, *oTh, *oTl;
    float* scores;
    cudaGetSymbolAddress((void**)&xh, g_xh);     cudaGetSymbolAddress((void**)&xl, g_xl);
    cudaGetSymbolAddress((void**)&wqh, g_wqh);   cudaGetSymbolAddress((void**)&wql, g_wql);
    cudaGetSymbolAddress((void**)&wph, g_wph);   cudaGetSymbolAddress((void**)&wpl, g_wpl);
    cudaGetSymbolAddress((void**)&qkvh, g_qkvh); cudaGetSymbolAddress((void**)&qkvl, g_qkvl);
    cudaGetSymbolAddress((void**)&scores, g_scores);
    cudaGetSymbolAddress((void**)&ph, g_ph);     cudaGetSymbolAddress((void**)&pl, g_pl);
    cudaGetSymbolAddress((void**)&vTh, g_vTh);   cudaGetSymbolAddress((void**)&vTl, g_vTl);
    cudaGetSymbolAddress((void**)&oh, g_oh);     cudaGetSymbolAddress((void**)&ol, g_ol);
    cudaGetSymbolAddress((void**)&oTh, g_oTh);   cudaGetSymbolAddress((void**)&oTl, g_oTl);

    const int shm128 = 3 * (2 * 128 * 128 + 32768);   // 196608
    const int shm64  = 3 * (2 * 64  * 128 + 32768);   // 147456
    cudaFuncSetAttribute(tc_gemm<0,4>, cudaFuncAttributeMaxDynamicSharedMemorySize, shm128);
    cudaFuncSetAttribute(tc_gemm<2,4>, cudaFuncAttributeMaxDynamicSharedMemorySize, shm128);
    cudaFuncSetAttribute(tc_gemm<1,2>, cudaFuncAttributeMaxDynamicSharedMemorySize, shm64);
    cudaFuncSetAttribute(tc_gemm<2,2>, cudaFuncAttributeMaxDynamicSharedMemorySize, shm64);

    const long long sQKV = (long long)SEQ * QKV3;
    const long long sSS  = (long long)SEQ * SEQ;
    const long long sSH  = (long long)SEQ * HSZ;
    const long long sHS  = (long long)HSZ * SEQ;

    // 0. split inputs into bf16 (hi, lo)
    split_kernel<<<1024, 256>>>(x,      xh,  xl,  (long long)BS * EMBED);
    split_kernel<<<512,  256>>>(w_qkv,  wqh, wql, (long long)QKV3 * EMBED);
    split_kernel<<<256,  256>>>(w_proj, wph, wpl, (long long)EMBED * HSZ);

    // 1. qkv = x @ w_qkv^T   [8192 x 3072 x 1024], split output. 1536 CTAs.
    tc_gemm<2,4><<<dim3(QKV3 / 128, BS / 128, 1), 256, shm128>>>(
        xh, xl, wqh, wql, nullptr, qkvh, qkvl, nullptr,
        EMBED, EMBED, EMBED, QKV3, 0, 0, 0, 1.0f);

    // 2. scores = 0.125 * q @ k^T   4x [2048 x 2048 x 1024]. 1024 CTAs.
    tc_gemm<0,4><<<dim3(SEQ / 128, SEQ / 128, BATCH), 256, shm128>>>(
        qkvh, qkvl, qkvh + HSZ, qkvl + HSZ, scores, nullptr, nullptr, nullptr,
        HSZ, QKV3, QKV3, SEQ, sQKV, sQKV, sSS, 0.125f);

    // 3. softmax -> split probs
    softmax_kernel<<<BATCH * SEQ, 256>>>(scores, ph, pl);

    // 4. vT = v^T per batch (v strided inside qkv split arrays)
    transpose_pair<<<dim3(HSZ / 32, SEQ / 32, BATCH), dim3(32, 8)>>>(
        qkvh + 2 * HSZ, qkvl + 2 * HSZ, vTh, vTl, QKV3, SEQ, sQKV, sHS);

    // 5. out = probs @ vT^T   4x [2048 x 1024 x 2048], BM=64. 1024 CTAs.
    tc_gemm<2,2><<<dim3(HSZ / 128, SEQ / 64, BATCH), 256, shm64>>>(
        ph, pl, vTh, vTl, nullptr, oh, ol, nullptr,
        SEQ, SEQ, SEQ, HSZ, sSS, sHS, sSH, 1.0f);

    // 6. scrambling reshape == per-batch transpose (flat re-view)
    transpose_pair<<<dim3(HSZ / 32, SEQ / 32, BATCH), dim3(32, 8)>>>(
        oh, ol, oTh, oTl, HSZ, SEQ, sSH, sHS);

    // 7. y = out2 @ w_proj^T + b   [8192 x 1024 x 1024], BM=64. 1024 CTAs.
    tc_gemm<1,2><<<dim3(EMBED / 128, BS / 64, 1), 256, shm64>>>(
        oTh, oTl, wph, wpl, y, nullptr, nullptr, b_proj,
        HSZ, HSZ, HSZ, EMBED, 0, 0, 0, 1.0f);
}